// round 5
// baseline (speedup 1.0000x reference)
#include <cuda_runtime.h>
#include <cstdint>

// Scratch for per-(batch,channel) generated 3x3 kernels: 16*64*9 floats.
__device__ float g_kern[16 * 576];

// ------------------------------ helpers ------------------------------------
__device__ __forceinline__ uint32_t f32_tf32(float f) {
    uint32_t u;
    asm("cvt.rna.tf32.f32 %0, %1;" : "=r"(u) : "f"(f));
    return u;
}

// D += A*B, m16n8k8 tf32 (tensor pipe, fp32 accumulate in registers)
__device__ __forceinline__ void mma_tf32(float* d, const uint32_t* a,
                                         const uint32_t* b) {
    asm volatile(
        "mma.sync.aligned.m16n8k8.row.col.f32.tf32.tf32.f32 "
        "{%0,%1,%2,%3}, {%4,%5,%6,%7}, {%8,%9}, {%0,%1,%2,%3};"
        : "+f"(d[0]), "+f"(d[1]), "+f"(d[2]), "+f"(d[3])
        : "r"(a[0]), "r"(a[1]), "r"(a[2]), "r"(a[3]), "r"(b[0]), "r"(b[1]));
}

// ---------------------------------------------------------------------------
// Kernel A: kernel-generating MLP. Grid 16 x 64 threads.
// ---------------------------------------------------------------------------
__global__ void gen_kern_kernel(const float* __restrict__ d,
                                const float* __restrict__ Wk1,
                                const float* __restrict__ Wk2) {
    const int b = blockIdx.x;
    const int t = threadIdx.x;  // 0..63
    __shared__ float ds[64];
    __shared__ float hid[64];

    ds[t] = d[b * 64 + t];
    __syncthreads();

    float s = 0.f;
#pragma unroll 16
    for (int i = 0; i < 64; i++) s += ds[i] * Wk1[t * 64 + i];
    hid[t] = (s >= 0.f) ? s : 0.1f * s;
    __syncthreads();

    for (int m = t; m < 576; m += 64) {
        float a = 0.f;
        const float* wp = Wk2 + (size_t)m * 64;
#pragma unroll 16
        for (int j = 0; j < 64; j++) a += hid[j] * wp[j];
        g_kern[b * 576 + m] = a;
    }
}

// ---------------------------------------------------------------------------
// Kernel B: fused dynamic depthwise 3x3 + LeakyReLU -> tf32 mma.sync GEMM
// (pointwise 1x1) + bias.
// Grid (4,16,16): block = 32x8 pixel tile of one batch, 256 threads (8 warps).
// GEMM: M=256 pixels, N=64 outputs, K=64 channels.
//   warps: 4 (M) x 2 (N); warp tile 64x32 = 4x4 m16n8k8 fragments;
//   B fragments register-resident across all K.
// Dynamic smem (bytes):
//   xs  @0      : halo, 64 ch x 10 rows x 34 cols f32            (87040)
//   vs  @87040  : V^T tf32, vs[k=c][m=pix], row stride 264       (67584)
//   wct @154624 : Wc tf32, wct[k=c][n=o],  row stride 72         (18432)
//   kk  @173056 : 64 x 12 f32 (3x3 kernels, padded)              ( 3072)
//   bcs @176128 : bias f32[64]                                   (  256)
// total 176384 -> 1 block/SM.
// Bank math: vs stride 264 -> A-frag bank = (8*tig + g) & 31 (conflict-free);
//            wct stride 72 -> B-frag bank = (8*tig + g) & 31 (conflict-free).
// ---------------------------------------------------------------------------
#define XS_OFF  0
#define VS_OFF  87040
#define WCT_OFF 154624
#define KK_OFF  173056
#define BC_OFF  176128
#define SMEM_TOTAL 176384
#define VS_STRIDE  264
#define WCT_STRIDE 72

__global__ __launch_bounds__(256, 1)
void da_conv_mma(const float* __restrict__ x,
                 const float* __restrict__ Wc,
                 const float* __restrict__ bc,
                 float* __restrict__ out) {
    extern __shared__ char smem[];
    float*    xs  = (float*)(smem + XS_OFF);
    uint32_t* vs  = (uint32_t*)(smem + VS_OFF);
    uint32_t* wct = (uint32_t*)(smem + WCT_OFF);
    float*    kk  = (float*)(smem + KK_OFF);
    float*    bcs = (float*)(smem + BC_OFF);

    const int t  = threadIdx.x;
    const int b  = blockIdx.z, bx = blockIdx.x, by = blockIdx.y;

    // Wc[o][c] (row-major) -> wct[k=c][n=o], tf32
    for (int i = t; i < 4096; i += 256) {
        int o = i >> 6, c = i & 63;
        wct[c * WCT_STRIDE + o] = f32_tf32(Wc[i]);
    }
    // generated 3x3 kernels for this batch, rows padded to 12
    for (int i = t; i < 576; i += 256) {
        int c = i / 9, j = i - c * 9;
        kk[c * 12 + j] = g_kern[b * 576 + i];
    }
    if (t < 64) bcs[t] = bc[t];

    // halo tile: 64 ch x 10 rows x 34 cols, zero-padded
    const int h0 = by * 8 - 1;
    const int w0 = bx * 32 - 1;
    const float* xb = x + (size_t)b * 64 * 16384;
    for (int i = t; i < 64 * 340; i += 256) {
        int c = i / 340;
        int rem = i - c * 340;
        int r = rem / 34, col = rem - r * 34;
        int gh = h0 + r, gw = w0 + col;
        float v = 0.f;
        if ((unsigned)gh < 128u && (unsigned)gw < 128u)
            v = xb[c * 16384 + gh * 128 + gw];
        xs[i] = v;
    }
    __syncthreads();

    // ------------- Phase 1: dwconv 3x3 + lrelu -> vs[k][m] (tf32) ----------
    {
        const int prow = t >> 5, pcol = t & 31;  // pixel (row,col) in 8x32 tile
        for (int c = 0; c < 64; c++) {
            const float* xc = xs + c * 340 + prow * 34 + pcol;
            float4 k0 = *reinterpret_cast<const float4*>(kk + c * 12);
            float4 k1 = *reinterpret_cast<const float4*>(kk + c * 12 + 4);
            float  k8 = kk[c * 12 + 8];

            float dw = xc[0]  * k0.x + xc[1]  * k0.y + xc[2]  * k0.z
                     + xc[34] * k0.w + xc[35] * k1.x + xc[36] * k1.y
                     + xc[68] * k1.z + xc[69] * k1.w + xc[70] * k8;
            float v = (dw >= 0.f) ? dw : 0.1f * dw;
            vs[c * VS_STRIDE + t] = f32_tf32(v);
        }
    }
    __syncthreads();

    // ------------- Phase 2: register-blocked tf32 tensor GEMM --------------
    const int w    = t >> 5;
    const int lane = t & 31;
    const int wm = w >> 1;          // 0..3 -> M offset
    const int wn = w & 1;           // 0..1 -> N offset
    const int g   = lane >> 2;      // groupID 0..7
    const int tig = lane & 3;       // thread-in-group 0..3
    const int m_base = wm * 64;
    const int n_base = wn * 32;

    // B fragments resident: bf[kstep][ntile][2]
    uint32_t bf[8][4][2];
#pragma unroll
    for (int s = 0; s < 8; s++)
#pragma unroll
        for (int nt = 0; nt < 4; nt++) {
            int n = n_base + nt * 8 + g;
            bf[s][nt][0] = wct[(s * 8 + tig) * WCT_STRIDE + n];
            bf[s][nt][1] = wct[(s * 8 + tig + 4) * WCT_STRIDE + n];
        }

    float acc[4][4][4];
#pragma unroll
    for (int mt = 0; mt < 4; mt++)
#pragma unroll
        for (int nt = 0; nt < 4; nt++)
#pragma unroll
            for (int r = 0; r < 4; r++) acc[mt][nt][r] = 0.f;

#pragma unroll
    for (int s = 0; s < 8; s++) {
        uint32_t af[4][4];
#pragma unroll
        for (int mt = 0; mt < 4; mt++) {
            int row0 = m_base + mt * 16 + g;
            int k0 = s * 8;
            af[mt][0] = vs[(k0 + tig) * VS_STRIDE + row0];
            af[mt][1] = vs[(k0 + tig) * VS_STRIDE + row0 + 8];
            af[mt][2] = vs[(k0 + tig + 4) * VS_STRIDE + row0];
            af[mt][3] = vs[(k0 + tig + 4) * VS_STRIDE + row0 + 8];
        }
#pragma unroll
        for (int mt = 0; mt < 4; mt++)
#pragma unroll
            for (int nt = 0; nt < 4; nt++)
                mma_tf32(acc[mt][nt], af[mt], bf[s][nt]);
    }

    // ------------- Epilogue: + bias -> GMEM --------------------------------
    float* ob = out + (size_t)b * 64 * 16384 + (size_t)(by * 8) * 128 + bx * 32;
#pragma unroll
    for (int mt = 0; mt < 4; mt++) {
        int pix0 = m_base + mt * 16 + g;       // pixel id 0..255
        int pix1 = pix0 + 8;
        int off0 = (pix0 >> 5) * 128 + (pix0 & 31);
        int off1 = (pix1 >> 5) * 128 + (pix1 & 31);
#pragma unroll
        for (int nt = 0; nt < 4; nt++) {
            int o0 = n_base + nt * 8 + 2 * tig;
            int o1 = o0 + 1;
            ob[o0 * 16384 + off0] = acc[mt][nt][0] + bcs[o0];
            ob[o1 * 16384 + off0] = acc[mt][nt][1] + bcs[o1];
            ob[o0 * 16384 + off1] = acc[mt][nt][2] + bcs[o0];
            ob[o1 * 16384 + off1] = acc[mt][nt][3] + bcs[o1];
        }
    }
}

// ---------------------------------------------------------------------------
// Launch: inputs x, d, Wk1, Wk2, Wc, bc. Output float32 (16,64,128,128).
// ---------------------------------------------------------------------------
extern "C" void kernel_launch(void* const* d_in, const int* in_sizes, int n_in,
                              void* d_out, int out_size) {
    const float* x   = (const float*)d_in[0];
    const float* d   = (const float*)d_in[1];
    const float* Wk1 = (const float*)d_in[2];
    const float* Wk2 = (const float*)d_in[3];
    const float* Wc  = (const float*)d_in[4];
    const float* bc  = (const float*)d_in[5];
    float* out = (float*)d_out;

    gen_kern_kernel<<<16, 64>>>(d, Wk1, Wk2);

    cudaFuncSetAttribute(da_conv_mma,
                         cudaFuncAttributeMaxDynamicSharedMemorySize,
                         SMEM_TOTAL);
    dim3 grid(4, 16, 16);
    da_conv_mma<<<grid, 256, SMEM_TOTAL>>>(x, Wc, bc, out);
}

// round 6
// speedup vs baseline: 1.8324x; 1.8324x over previous
#include <cuda_runtime.h>
#include <cstdint>

// Scratch for per-(batch,channel) generated 3x3 kernels: 16*64*9 floats.
__device__ float g_kern[16 * 576];

// ------------------------------ helpers ------------------------------------
__device__ __forceinline__ uint32_t f32_tf32(float f) {
    uint32_t u;
    asm("cvt.rna.tf32.f32 %0, %1;" : "=r"(u) : "f"(f));
    return u;
}
__device__ __forceinline__ uint32_t smem_u32(const void* p) {
    uint32_t a;
    asm("{ .reg .u64 t; cvta.to.shared.u64 t, %1; cvt.u32.u64 %0, t; }"
        : "=r"(a) : "l"(p));
    return a;
}
__device__ __forceinline__ void cp_async4(uint32_t saddr, const void* gaddr,
                                          uint32_t src_sz) {
    asm volatile("cp.async.ca.shared.global [%0], [%1], 4, %2;"
                 :: "r"(saddr), "l"(gaddr), "r"(src_sz) : "memory");
}
#define CP_COMMIT() asm volatile("cp.async.commit_group;" ::: "memory")
#define CP_WAIT(n)  asm volatile("cp.async.wait_group %0;" :: "n"(n) : "memory")

// D += A*B, m16n8k8 tf32 (tensor pipe, fp32 accumulate in registers)
__device__ __forceinline__ void mma_tf32(float* d, const uint32_t* a,
                                         const uint32_t* b) {
    asm volatile(
        "mma.sync.aligned.m16n8k8.row.col.f32.tf32.tf32.f32 "
        "{%0,%1,%2,%3}, {%4,%5,%6,%7}, {%8,%9}, {%0,%1,%2,%3};"
        : "+f"(d[0]), "+f"(d[1]), "+f"(d[2]), "+f"(d[3])
        : "r"(a[0]), "r"(a[1]), "r"(a[2]), "r"(a[3]), "r"(b[0]), "r"(b[1]));
}

// ---------------------------------------------------------------------------
// Kernel A: kernel-generating MLP. Grid 16 x 64 threads.
// ---------------------------------------------------------------------------
__global__ void gen_kern_kernel(const float* __restrict__ d,
                                const float* __restrict__ Wk1,
                                const float* __restrict__ Wk2) {
    const int b = blockIdx.x;
    const int t = threadIdx.x;  // 0..63
    __shared__ float ds[64];
    __shared__ float hid[64];

    ds[t] = d[b * 64 + t];
    __syncthreads();

    float s = 0.f;
#pragma unroll 16
    for (int i = 0; i < 64; i++) s += ds[i] * Wk1[t * 64 + i];
    hid[t] = (s >= 0.f) ? s : 0.1f * s;
    __syncthreads();

    for (int m = t; m < 576; m += 64) {
        float a = 0.f;
        const float* wp = Wk2 + (size_t)m * 64;
#pragma unroll 16
        for (int j = 0; j < 64; j++) a += hid[j] * wp[j];
        g_kern[b * 576 + m] = a;
    }
}

// ---------------------------------------------------------------------------
// Kernel B: fused dynamic depthwise 3x3 + LeakyReLU -> tf32 mma.sync GEMM
// (pointwise 1x1) + bias, channel-chunked with cp.async double buffering.
//
// Grid (4,16,16): block = 32x8 pixel tile of one batch, 256 threads (8 warps).
// GEMM: M=256 pixels, N=64 outputs, K=64 channels, processed in 4 chunks of 16.
// Smem (bytes):
//   xs[2]  @0      : halo chunk, 16ch x 10r x 34c f32, 2 bufs   (43520)
//   vs[2]  @43520  : V^T tf32, [k=0..15][m=pix] stride 264      (33792)
//                    (reused after GEMM as 32x264 epilogue stage)
//   wct    @77312  : Wc tf32, [k=c][n=o] stride 72              (18432)
//   kk     @95744  : 64 x 12 f32                                ( 3072)
//   bcs    @98816  : bias f32[64]                               (  256)
// total 99072 -> 2 blocks/SM (occ 25%).
// ---------------------------------------------------------------------------
#define KC          16
#define XS_OFF      0
#define XS_BUF      21760            // 16*340*4
#define VS_OFF      43520
#define VS_BUF      16896            // 16*264*4
#define WCT_OFF     77312
#define KK_OFF      95744
#define BC_OFF      98816
#define SMEM_TOTAL  99072
#define VS_STRIDE   264
#define WCT_STRIDE  72

__global__ __launch_bounds__(256, 2)
void da_conv_mma(const float* __restrict__ x,
                 const float* __restrict__ Wc,
                 const float* __restrict__ bc,
                 float* __restrict__ out) {
    extern __shared__ char smem[];
    const uint32_t smb = smem_u32(smem);
    uint32_t* wct = (uint32_t*)(smem + WCT_OFF);
    float*    kk  = (float*)(smem + KK_OFF);
    float*    bcs = (float*)(smem + BC_OFF);
    float*    stage = (float*)(smem + VS_OFF);   // epilogue reuse

    const int t  = threadIdx.x;
    const int b  = blockIdx.z, bx = blockIdx.x, by = blockIdx.y;
    const int w  = t >> 5, lane = t & 31;

    // ---- static tiles: Wc -> wct (tf32), kernels, bias --------------------
    for (int i = t; i < 4096; i += 256) {
        int o = i >> 6, c = i & 63;
        wct[c * WCT_STRIDE + o] = f32_tf32(Wc[i]);
    }
    for (int i = t; i < 576; i += 256) {
        int c = i / 9, j = i - c * 9;
        kk[c * 12 + j] = g_kern[b * 576 + i];
    }
    if (t < 64) bcs[t] = bc[t];

    // ---- halo chunk loader (cp.async, zero-fill OOB via src-size) ---------
    const int h0 = by * 8 - 1;
    const int w0 = bx * 32 - 1;
    const float* xb = x + (size_t)b * 64 * 16384;
    const int gw1 = w0 + lane;         // col this lane loads
    const int gw2 = w0 + 32 + lane;    // tail col (lanes 0,1 only)
    const bool gw1ok = (unsigned)gw1 < 128u;
    const bool gw2ok = (lane < 2) && ((unsigned)gw2 < 128u);

    auto load_chunk = [&](int chunk, int buf) {
        uint32_t xsb = smb + XS_OFF + buf * XS_BUF;
        // 160 (ch,row) pairs; warp w handles pairs w, w+8, ...
#pragma unroll 4
        for (int j = 0; j < 20; j++) {
            int pair = w + 8 * j;
            int c = pair / 10, r = pair - c * 10;
            int gh = h0 + r;
            bool hok = (unsigned)gh < 128u;
            const float* gsrc = xb + (size_t)(chunk * KC + c) * 16384 +
                                (hok ? gh * 128 : 0);
            uint32_t sdst = xsb + (uint32_t)(c * 340 + r * 34 + lane) * 4;
            cp_async4(sdst, gsrc + (gw1ok ? gw1 : 0),
                      (hok && gw1ok) ? 4u : 0u);
            if (lane < 2)
                cp_async4(sdst + 128, gsrc + (gw2ok ? gw2 : 0),
                          (hok && gw2ok) ? 4u : 0u);
        }
        CP_COMMIT();
    };

    load_chunk(0, 0);
    load_chunk(1, 1);

    // ---- GEMM thread mapping (identical fragment layout to R5) ------------
    const int wm = w >> 1, wn = w & 1;
    const int g = lane >> 2, tig = lane & 3;
    const int m_base = wm * 64;
    const int n_base = wn * 32;

    float acc[4][4][4];
#pragma unroll
    for (int mt = 0; mt < 4; mt++)
#pragma unroll
        for (int nt = 0; nt < 4; nt++)
#pragma unroll
            for (int r = 0; r < 4; r++) acc[mt][nt][r] = 0.f;

    const int prow = w;                 // phase-1: warp = one 32-wide pixel row
    const int pcol = lane;

#pragma unroll
    for (int c = 0; c < 4; c++) {
        const int buf = c & 1;
        if (c < 3) { CP_WAIT(1); } else { CP_WAIT(0); }
        __syncthreads();

        // ---- phase 1: dwconv 3x3 + lrelu on this 16-channel chunk ---------
        float* xs = (float*)(smem + XS_OFF + buf * XS_BUF);
        uint32_t* vs = (uint32_t*)(smem + VS_OFF + buf * VS_BUF);
        const float* kkc = kk + c * KC * 12;
#pragma unroll
        for (int cl = 0; cl < KC; cl++) {
            const float* xc = xs + cl * 340 + prow * 34 + pcol;
            float4 k0 = *reinterpret_cast<const float4*>(kkc + cl * 12);
            float4 k1 = *reinterpret_cast<const float4*>(kkc + cl * 12 + 4);
            float  k8 = kkc[cl * 12 + 8];

            float dw = xc[0]  * k0.x + xc[1]  * k0.y + xc[2]  * k0.z
                     + xc[34] * k0.w + xc[35] * k1.x + xc[36] * k1.y
                     + xc[68] * k1.z + xc[69] * k1.w + xc[70] * k8;
            float v = (dw >= 0.f) ? dw : 0.1f * dw;
            vs[cl * VS_STRIDE + t] = f32_tf32(v);
        }
        __syncthreads();

        // prefetch chunk c+2 into the buffer we just drained
        if (c < 2) load_chunk(c + 2, buf);

        // ---- phase 2: 2 k-steps of the tf32 tensor GEMM -------------------
#pragma unroll
        for (int s2 = 0; s2 < 2; s2++) {
            const int k0 = s2 * 8;
            uint32_t bf[4][2];
#pragma unroll
            for (int nt = 0; nt < 4; nt++) {
                int n = n_base + nt * 8 + g;
                bf[nt][0] = wct[(c * KC + k0 + tig) * WCT_STRIDE + n];
                bf[nt][1] = wct[(c * KC + k0 + tig + 4) * WCT_STRIDE + n];
            }
            uint32_t af[4][4];
#pragma unroll
            for (int mt = 0; mt < 4; mt++) {
                int row0 = m_base + mt * 16 + g;
                af[mt][0] = vs[(k0 + tig) * VS_STRIDE + row0];
                af[mt][1] = vs[(k0 + tig) * VS_STRIDE + row0 + 8];
                af[mt][2] = vs[(k0 + tig + 4) * VS_STRIDE + row0];
                af[mt][3] = vs[(k0 + tig + 4) * VS_STRIDE + row0 + 8];
            }
#pragma unroll
            for (int mt = 0; mt < 4; mt++)
#pragma unroll
                for (int nt = 0; nt < 4; nt++)
                    mma_tf32(acc[mt][nt], af[mt], bf[nt]);
        }
    }

    // ---- epilogue: stage through smem -> coalesced STG --------------------
    float* obase = out + (size_t)b * 64 * 16384 + (size_t)(by * 8) * 128 + bx * 32;
    __syncthreads();
#pragma unroll
    for (int nc = 0; nc < 2; nc++) {
        if (wn == nc) {
#pragma unroll
            for (int mt = 0; mt < 4; mt++)
#pragma unroll
                for (int nt = 0; nt < 4; nt++) {
                    int ol = nt * 8 + 2 * tig;
                    int p0 = m_base + mt * 16 + g;
                    stage[ol * VS_STRIDE + p0]            = acc[mt][nt][0];
                    stage[(ol + 1) * VS_STRIDE + p0]      = acc[mt][nt][1];
                    stage[ol * VS_STRIDE + p0 + 8]        = acc[mt][nt][2];
                    stage[(ol + 1) * VS_STRIDE + p0 + 8]  = acc[mt][nt][3];
                }
        }
        __syncthreads();
#pragma unroll 8
        for (int j = 0; j < 32; j++) {
            int idx = t + 256 * j;
            int ol = idx >> 8, pix = idx & 255;
            float v = stage[ol * VS_STRIDE + pix] + bcs[nc * 32 + ol];
            obase[(size_t)(nc * 32 + ol) * 16384 + (pix >> 5) * 128 + (pix & 31)] = v;
        }
        __syncthreads();
    }
}

// ---------------------------------------------------------------------------
// Launch: inputs x, d, Wk1, Wk2, Wc, bc. Output float32 (16,64,128,128).
// ---------------------------------------------------------------------------
extern "C" void kernel_launch(void* const* d_in, const int* in_sizes, int n_in,
                              void* d_out, int out_size) {
    const float* x   = (const float*)d_in[0];
    const float* d   = (const float*)d_in[1];
    const float* Wk1 = (const float*)d_in[2];
    const float* Wk2 = (const float*)d_in[3];
    const float* Wc  = (const float*)d_in[4];
    const float* bc  = (const float*)d_in[5];
    float* out = (float*)d_out;

    gen_kern_kernel<<<16, 64>>>(d, Wk1, Wk2);

    cudaFuncSetAttribute(da_conv_mma,
                         cudaFuncAttributeMaxDynamicSharedMemorySize,
                         SMEM_TOTAL);
    dim3 grid(4, 16, 16);
    da_conv_mma<<<grid, 256, SMEM_TOTAL>>>(x, Wc, bc, out);
}

// round 7
// speedup vs baseline: 2.9031x; 1.5843x over previous
#include <cuda_runtime.h>
#include <cstdint>

// Scratch for per-(batch,channel) generated 3x3 kernels: 16*64*9 floats.
__device__ float g_kern[16 * 576];

// ------------------------------ helpers ------------------------------------
__device__ __forceinline__ uint32_t f32_tf32(float f) {
    uint32_t u;
    asm("cvt.rna.tf32.f32 %0, %1;" : "=r"(u) : "f"(f));
    return u;
}
__device__ __forceinline__ uint32_t smem_u32(const void* p) {
    uint32_t a;
    asm("{ .reg .u64 t; cvta.to.shared.u64 t, %1; cvt.u32.u64 %0, t; }"
        : "=r"(a) : "l"(p));
    return a;
}
__device__ __forceinline__ void cp_async16(uint32_t saddr, const void* gaddr,
                                           uint32_t src_sz) {
    asm volatile("cp.async.cg.shared.global [%0], [%1], 16, %2;"
                 :: "r"(saddr), "l"(gaddr), "r"(src_sz) : "memory");
}
#define CP_COMMIT() asm volatile("cp.async.commit_group;" ::: "memory")
#define CP_WAIT(n)  asm volatile("cp.async.wait_group %0;" :: "n"(n) : "memory")

// D += A*B, m16n8k8 tf32 (tensor pipe, fp32 accumulate in registers)
__device__ __forceinline__ void mma_tf32(float* d, const uint32_t* a,
                                         const uint32_t* b) {
    asm volatile(
        "mma.sync.aligned.m16n8k8.row.col.f32.tf32.tf32.f32 "
        "{%0,%1,%2,%3}, {%4,%5,%6,%7}, {%8,%9}, {%0,%1,%2,%3};"
        : "+f"(d[0]), "+f"(d[1]), "+f"(d[2]), "+f"(d[3])
        : "r"(a[0]), "r"(a[1]), "r"(a[2]), "r"(a[3]), "r"(b[0]), "r"(b[1]));
}

// ---------------------------------------------------------------------------
// Kernel A: kernel-generating MLP. Grid (16,9) x 64 threads; block (b,mb)
// computes outputs m = mb*64 .. mb*64+63 (576 = 9*64). hid recomputed per
// block (4K FMA, trivial) to maximize SM parallelism.
// ---------------------------------------------------------------------------
__global__ void gen_kern_kernel(const float* __restrict__ d,
                                const float* __restrict__ Wk1,
                                const float* __restrict__ Wk2) {
    const int b = blockIdx.x;
    const int t = threadIdx.x;  // 0..63
    __shared__ float ds[64];
    __shared__ float hid[64];

    ds[t] = d[b * 64 + t];
    __syncthreads();

    float s = 0.f;
#pragma unroll 16
    for (int i = 0; i < 64; i++) s += ds[i] * Wk1[t * 64 + i];
    hid[t] = (s >= 0.f) ? s : 0.1f * s;
    __syncthreads();

    const int m = blockIdx.y * 64 + t;
    float a = 0.f;
    const float* wp = Wk2 + (size_t)m * 64;
#pragma unroll 16
    for (int j = 0; j < 64; j++) a += hid[j] * wp[j];
    g_kern[b * 576 + m] = a;
}

// ---------------------------------------------------------------------------
// Kernel B: fused dynamic depthwise 3x3 + LeakyReLU -> tf32 mma.sync GEMM
// (pointwise 1x1) + bias; channel-chunked cp.async pipeline, vectorized
// phase 1 (8 px/thread/channel, float4 LDS).
//
// Grid (4,16,16): block = 32x8 pixel tile of one batch, 256 threads (8 warps).
// GEMM: M=256 pixels, N=64 outputs, K=64 channels, 4 chunks of 16.
// Smem (bytes):
//   xs[2] @0     : halo chunk, 16ch x 10r x 44f (stride 176B), 2 bufs (56320)
//                  (region reused as 32x264 epilogue stage after GEMM)
//   vs    @56320 : V^T tf32, [k=0..15][m=pix] stride 264            (16896)
//   wct   @73216 : Wc tf32, [k=c][n=o] stride 72                    (18432)
//   kk    @91648 : 64 x 12 f32                                      ( 3072)
//   bcs   @94720 : bias f32[64]                                     (  256)
// total 94976 -> 2 blocks/SM.
// ---------------------------------------------------------------------------
#define KC          16
#define XS_OFF      0
#define XS_BUF      28160            // 16*440*4
#define VS_OFF      56320
#define WCT_OFF     73216
#define KK_OFF      91648
#define BC_OFF      94720
#define SMEM_TOTAL  94976
#define VS_STRIDE   264
#define WCT_STRIDE  72

__global__ __launch_bounds__(256, 2)
void da_conv_mma(const float* __restrict__ x,
                 const float* __restrict__ Wc,
                 const float* __restrict__ bc,
                 float* __restrict__ out) {
    extern __shared__ char smem[];
    const uint32_t smb = smem_u32(smem);
    uint32_t* wct = (uint32_t*)(smem + WCT_OFF);
    float*    kk  = (float*)(smem + KK_OFF);
    float*    bcs = (float*)(smem + BC_OFF);
    uint32_t* vs  = (uint32_t*)(smem + VS_OFF);
    float*    stage = (float*)(smem + XS_OFF);   // epilogue reuse

    const int t  = threadIdx.x;
    const int b  = blockIdx.z, bx = blockIdx.x, by = blockIdx.y;
    const int w  = t >> 5, lane = t & 31;

    // ---- static tiles: Wc -> wct (tf32), kernels, bias --------------------
    for (int i = t; i < 4096; i += 256) {
        int o = i >> 6, c = i & 63;
        wct[c * WCT_STRIDE + o] = f32_tf32(Wc[i]);
    }
    for (int i = t; i < 576; i += 256) {
        int c = i / 9, j = i - c * 9;
        kk[c * 12 + j] = g_kern[b * 576 + i];
    }
    if (t < 64) bcs[t] = bc[t];

    // ---- halo loader: 16B cp.async, slab mapping (threads 0..159) ---------
    // xs row = 44 floats; data cols 0..39 = gw w0-4 .. w0+35 (10 x 16B chunks)
    const int h0  = by * 8 - 1;
    const int w0p = bx * 32;
    const float* xb = x + (size_t)b * 64 * 16384;

    const int  lcl = t & 15;            // channel-in-chunk this thread loads
    const int  lk  = t >> 4;            // 16B chunk index 0..9 (t<160)
    const int  cb  = w0p - 4 + lk * 4;  // global col of chunk start
    const bool vc  = (unsigned)cb <= 124u;
    const bool lactive = t < 160;
    const float* lsrc0 = xb + (size_t)lcl * 16384 + (vc ? cb : 0);
    const uint32_t ldst0 = smb + XS_OFF + (uint32_t)(lcl * 1760 + lk * 16);

    auto load_chunk = [&](int c, int buf) {
        if (lactive) {
            const float* s0 = lsrc0 + (size_t)c * KC * 16384;
            uint32_t d0 = ldst0 + (uint32_t)buf * XS_BUF;
#pragma unroll
            for (int r = 0; r < 10; r++) {
                int gh = h0 + r;
                bool v = vc && ((unsigned)gh < 128u);
                cp_async16(d0 + r * 176, s0 + (v ? gh * 128 : 0), v ? 16u : 0u);
            }
        }
        CP_COMMIT();
    };

    load_chunk(0, 0);
    load_chunk(1, 1);

    // ---- GEMM thread mapping (fragment layout verified in R5/R6) ----------
    const int wm = w >> 1, wn = w & 1;
    const int g = lane >> 2, tig = lane & 3;
    const int m_base = wm * 64;
    const int n_base = wn * 32;

    float acc[4][4][4];
#pragma unroll
    for (int mt = 0; mt < 4; mt++)
#pragma unroll
        for (int nt = 0; nt < 4; nt++)
#pragma unroll
            for (int r = 0; r < 4; r++) acc[mt][nt][r] = 0.f;

    // ---- phase-1 mapping: thread -> 8 consecutive pixels, 2 channels ------
    const int p_cl0 = t >> 5;           // unit channels: p_cl0, p_cl0+8
    const int px0   = (t & 31) * 8;     // pixel base 0..248
    const int R     = px0 >> 5;         // tile row 0..7
    const int P0    = px0 & 31;         // col base 0,8,16,24

#pragma unroll
    for (int c = 0; c < 4; c++) {
        const int buf = c & 1;
        if (c < 3) { CP_WAIT(1); } else { CP_WAIT(0); }
        __syncthreads();

        // ---- phase 1: dwconv 3x3 + lrelu, 8px x 2ch per thread ------------
        float* xs = (float*)(smem + XS_OFF + buf * XS_BUF);
#pragma unroll
        for (int u = 0; u < 2; u++) {
            const int cl = p_cl0 + u * 8;
            const float* kc = kk + (c * KC + cl) * 12;
            float4 ka = *(const float4*)kc;        // k0..k3
            float4 kb = *(const float4*)(kc + 4);  // k4..k7
            float  k8 = kc[8];
            const float* xrow = xs + cl * 440 + R * 44 + P0;

            float a8[8];
#pragma unroll
            for (int p = 0; p < 8; p++) a8[p] = 0.f;

#pragma unroll
            for (int r = 0; r < 3; r++) {
                float kr0 = (r == 0) ? ka.x : (r == 1) ? ka.w : kb.z;
                float kr1 = (r == 0) ? ka.y : (r == 1) ? kb.x : kb.w;
                float kr2 = (r == 0) ? ka.z : (r == 1) ? kb.y : k8;
                const float* xr = xrow + r * 44;
                float4 x0 = *(const float4*)(xr);
                float4 x1 = *(const float4*)(xr + 4);
                float4 x2 = *(const float4*)(xr + 8);
                float4 x3 = *(const float4*)(xr + 12);
                float v[16] = {x0.x, x0.y, x0.z, x0.w, x1.x, x1.y, x1.z, x1.w,
                               x2.x, x2.y, x2.z, x2.w, x3.x, x3.y, x3.z, x3.w};
#pragma unroll
                for (int p = 0; p < 8; p++)
                    a8[p] += v[3 + p] * kr0 + v[4 + p] * kr1 + v[5 + p] * kr2;
            }

            uint32_t o8[8];
#pragma unroll
            for (int p = 0; p < 8; p++) {
                float vv = (a8[p] >= 0.f) ? a8[p] : 0.1f * a8[p];
                o8[p] = f32_tf32(vv);
            }
            uint4* dst = (uint4*)(vs + cl * VS_STRIDE + px0);
            dst[0] = make_uint4(o8[0], o8[1], o8[2], o8[3]);
            dst[1] = make_uint4(o8[4], o8[5], o8[6], o8[7]);
        }
        __syncthreads();

        // prefetch chunk c+2 into the buffer we just drained
        if (c < 2) load_chunk(c + 2, buf);

        // ---- phase 2: 2 k-steps of the tf32 tensor GEMM -------------------
#pragma unroll
        for (int s2 = 0; s2 < 2; s2++) {
            const int k0 = s2 * 8;
            uint32_t bf[4][2];
#pragma unroll
            for (int nt = 0; nt < 4; nt++) {
                int n = n_base + nt * 8 + g;
                bf[nt][0] = wct[(c * KC + k0 + tig) * WCT_STRIDE + n];
                bf[nt][1] = wct[(c * KC + k0 + tig + 4) * WCT_STRIDE + n];
            }
            uint32_t af[4][4];
#pragma unroll
            for (int mt = 0; mt < 4; mt++) {
                int row0 = m_base + mt * 16 + g;
                af[mt][0] = vs[(k0 + tig) * VS_STRIDE + row0];
                af[mt][1] = vs[(k0 + tig) * VS_STRIDE + row0 + 8];
                af[mt][2] = vs[(k0 + tig + 4) * VS_STRIDE + row0];
                af[mt][3] = vs[(k0 + tig + 4) * VS_STRIDE + row0 + 8];
            }
#pragma unroll
            for (int mt = 0; mt < 4; mt++)
#pragma unroll
                for (int nt = 0; nt < 4; nt++)
                    mma_tf32(acc[mt][nt], af[mt], bf[nt]);
        }
    }

    // ---- epilogue: stage through smem (xs region, now free) -> STG --------
    float* obase = out + (size_t)b * 64 * 16384 + (size_t)(by * 8) * 128 + bx * 32;
    __syncthreads();
#pragma unroll
    for (int nc = 0; nc < 2; nc++) {
        if (wn == nc) {
#pragma unroll
            for (int mt = 0; mt < 4; mt++)
#pragma unroll
                for (int nt = 0; nt < 4; nt++) {
                    int ol = nt * 8 + 2 * tig;
                    int p0 = m_base + mt * 16 + g;
                    stage[ol * VS_STRIDE + p0]            = acc[mt][nt][0];
                    stage[(ol + 1) * VS_STRIDE + p0]      = acc[mt][nt][1];
                    stage[ol * VS_STRIDE + p0 + 8]        = acc[mt][nt][2];
                    stage[(ol + 1) * VS_STRIDE + p0 + 8]  = acc[mt][nt][3];
                }
        }
        __syncthreads();
#pragma unroll 8
        for (int j = 0; j < 32; j++) {
            int idx = t + 256 * j;
            int ol = idx >> 8, pix = idx & 255;
            float v = stage[ol * VS_STRIDE + pix] + bcs[nc * 32 + ol];
            obase[(size_t)(nc * 32 + ol) * 16384 + (pix >> 5) * 128 + (pix & 31)] = v;
        }
        __syncthreads();
    }
}

// ---------------------------------------------------------------------------
// Launch: inputs x, d, Wk1, Wk2, Wc, bc. Output float32 (16,64,128,128).
// ---------------------------------------------------------------------------
extern "C" void kernel_launch(void* const* d_in, const int* in_sizes, int n_in,
                              void* d_out, int out_size) {
    const float* x   = (const float*)d_in[0];
    const float* d   = (const float*)d_in[1];
    const float* Wk1 = (const float*)d_in[2];
    const float* Wk2 = (const float*)d_in[3];
    const float* Wc  = (const float*)d_in[4];
    const float* bc  = (const float*)d_in[5];
    float* out = (float*)d_out;

    gen_kern_kernel<<<dim3(16, 9), 64>>>(d, Wk1, Wk2);

    cudaFuncSetAttribute(da_conv_mma,
                         cudaFuncAttributeMaxDynamicSharedMemorySize,
                         SMEM_TOTAL);
    dim3 grid(4, 16, 16);
    da_conv_mma<<<grid, 256, SMEM_TOTAL>>>(x, Wc, bc, out);
}